// round 9
// baseline (speedup 1.0000x reference)
#include <cuda_runtime.h>
#include <cuda_fp16.h>
#include <cstdint>

// Problem constants
#define Q      1024
#define D      512
#define NPTS   50000
#define BM     128
#define BN     128
#define BK     32
#define ITERS  (D / BK)                 // 16
#define NTILES ((NPTS + BN - 1) / BN)   // 391
#define PITCH  (NTILES * BN)            // 50048
#define KNN    10
#define PAD    40                       // padded smem row stride in b16 units (80B)

// FFMA tile predicate: every 8th N-tile below 320 (40 tiles, all in-bounds)
#define IS_FFMA_TILE(x) (((x) & 7) == 7 && (x) < 320)

// Scratch (device globals: allocation-free rule)
__device__ float   g_dot[(size_t)Q * PITCH];   // approx sq distances (~205 MB)
__device__ float   g_x2[Q];
__device__ float   g_d2[NPTS];
__device__ __half  g_xh[(size_t)Q * D];
__device__ __half  g_dh[(size_t)NPTS * D];

// ---------------------------------------------------------------------------
// helpers
// ---------------------------------------------------------------------------
__device__ __forceinline__ uint32_t smem_u32(const void* p) {
    uint32_t a;
    asm("{ .reg .u64 t; cvta.to.shared.u64 t, %1; cvt.u32.u64 %0, t; }" : "=r"(a) : "l"(p));
    return a;
}
__device__ __forceinline__ void cp_async16(uint32_t saddr, const void* gaddr, uint32_t src_sz) {
    asm volatile("cp.async.cg.shared.global [%0], [%1], 16, %2;"
                 :: "r"(saddr), "l"(gaddr), "r"(src_sz) : "memory");
}
__device__ __forceinline__ void cp_commit() {
    asm volatile("cp.async.commit_group;" ::: "memory");
}
template <int N>
__device__ __forceinline__ void cp_wait() {
    asm volatile("cp.async.wait_group %0;" :: "n"(N) : "memory");
}
__device__ __forceinline__ void ldm_x4(uint32_t& r0, uint32_t& r1, uint32_t& r2, uint32_t& r3,
                                       uint32_t addr) {
    asm volatile("ldmatrix.sync.aligned.m8n8.x4.shared.b16 {%0,%1,%2,%3}, [%4];"
                 : "=r"(r0), "=r"(r1), "=r"(r2), "=r"(r3) : "r"(addr));
}
// f16 x f16 -> f16 accum: D/C are 2 b32 regs, each packing {c0,c1} / {c2,c3}
__device__ __forceinline__ void mma_f16acc(uint32_t& d0, uint32_t& d1,
                                           uint32_t a0, uint32_t a1, uint32_t a2, uint32_t a3,
                                           uint32_t b0, uint32_t b1) {
    asm volatile(
        "mma.sync.aligned.m16n8k16.row.col.f16.f16.f16.f16 "
        "{%0,%1}, {%2,%3,%4,%5}, {%6,%7}, {%0,%1};"
        : "+r"(d0), "+r"(d1)
        : "r"(a0), "r"(a1), "r"(a2), "r"(a3), "r"(b0), "r"(b1));
}

// ---------------------------------------------------------------------------
// Kernel 0: fused fp32->fp16 convert + row squared norms (warp per row)
// ---------------------------------------------------------------------------
__global__ void convert_norms_kernel(const float* __restrict__ X,
                                     const float* __restrict__ data)
{
    int warp = (blockIdx.x * blockDim.x + threadIdx.x) >> 5;
    int lane = threadIdx.x & 31;
    if (warp >= Q + NPTS) return;

    const float* src;
    __half*      dsth;
    float*       dstn;
    int row;
    if (warp < Q) { src = X;    row = warp;     dsth = g_xh; dstn = g_x2; }
    else          { src = data; row = warp - Q; dsth = g_dh; dstn = g_d2; }

    const float4* s4 = (const float4*)(src + (size_t)row * D);
    uint2*        d8 = (uint2*)(dsth + (size_t)row * D);

    float s = 0.f;
    #pragma unroll
    for (int it = 0; it < 4; ++it) {
        int i = it * 32 + lane;
        float4 v = s4[i];
        s = fmaf(v.x, v.x, s);
        s = fmaf(v.y, v.y, s);
        s = fmaf(v.z, v.z, s);
        s = fmaf(v.w, v.w, s);
        __half2 h0 = __floats2half2_rn(v.x, v.y);
        __half2 h1 = __floats2half2_rn(v.z, v.w);
        uint2 w;
        w.x = *reinterpret_cast<uint32_t*>(&h0);
        w.y = *reinterpret_cast<uint32_t*>(&h1);
        d8[i] = w;
    }
    #pragma unroll
    for (int off = 16; off; off >>= 1)
        s += __shfl_down_sync(0xffffffffu, s, off);
    if (lane == 0) dstn[row] = s;
}

// ---------------------------------------------------------------------------
// Kernel 1: hybrid GEMM. HMMA CTAs (f16 mma.sync, tensor pipe) handle most
// N-tiles; FFMA CTAs (exact fp32 SGEMM, fma pipe) handle every 8th tile.
// Both write score = max(x2 + d2 - 2*dot, 0) to g_dot (fp32).
// ---------------------------------------------------------------------------
__global__ void __launch_bounds__(256, 2) gemm_hybrid_kernel(const float* __restrict__ Af,
                                                             const float* __restrict__ Bf)
{
    // 40KB shared: HMMA uses as 2 x (A 10240B + B 10240B); FFMA reinterprets.
    __shared__ __align__(16) uint16_t sm[2][BM * PAD + BN * PAD];

    const int tid = threadIdx.x;
    const int bx  = blockIdx.x;
    const int bn  = bx * BN;
    const int bm  = blockIdx.y * BM;

    if (!IS_FFMA_TILE(bx)) {
        // =================== HMMA path (f16 accum) ===================
        const int wid    = tid >> 5;
        const int lane   = tid & 31;
        const int warp_m = wid >> 2;
        const int warp_n = wid & 3;

        const int r0 = tid >> 2,         c0 = tid & 3;
        const int r1 = (tid + 256) >> 2, c1 = (tid + 256) & 3;

        const uint32_t sA  = smem_u32(&sm[0][0]);
        const uint32_t sB  = sA + BM * PAD * 2;
        const uint32_t BUF = (BM * PAD + BN * PAD) * 2;   // bytes per stage

        const uint32_t aS0 = sA + (r0 * PAD + c0 * 8) * 2;
        const uint32_t aS1 = sA + (r1 * PAD + c1 * 8) * 2;
        const uint32_t bS0 = sB + (r0 * PAD + c0 * 8) * 2;
        const uint32_t bS1 = sB + (r1 * PAD + c1 * 8) * 2;
        const size_t   aG0 = (size_t)(bm + r0) * D + c0 * 8;
        const size_t   aG1 = (size_t)(bm + r1) * D + c1 * 8;
        const size_t   bG0 = (size_t)(bn + r0) * D + c0 * 8;
        const size_t   bG1 = (size_t)(bn + r1) * D + c1 * 8;
        const uint32_t bV0 = (bn + r0 < NPTS) ? 16u : 0u;
        const uint32_t bV1 = (bn + r1 < NPTS) ? 16u : 0u;

        const uint32_t aLd = sA + (((warp_m * 64) + (lane & 15)) * PAD + (lane >> 4) * 8) * 2;
        const uint32_t bLd = sB + (((warp_n * 32) + (lane & 7)) * PAD + (lane >> 3) * 8) * 2;

        uint32_t acc[4][4][2];   // f16x2 accumulators
        #pragma unroll
        for (int i = 0; i < 4; ++i)
            #pragma unroll
            for (int j = 0; j < 4; ++j)
                acc[i][j][0] = acc[i][j][1] = 0u;

        // prologue: iter 0 -> buf 0
        cp_async16(aS0, g_xh + aG0, 16);
        cp_async16(aS1, g_xh + aG1, 16);
        cp_async16(bS0, g_dh + bG0, bV0);
        cp_async16(bS1, g_dh + bG1, bV1);
        cp_commit();

        for (int it = 0; it < ITERS; ++it) {
            const uint32_t off = (it & 1) ? BUF : 0;

            if (it + 1 < ITERS) {
                const uint32_t nf = ((it + 1) & 1) ? BUF : 0;
                const int      k0 = (it + 1) * BK;
                cp_async16(aS0 + nf, g_xh + aG0 + k0, 16);
                cp_async16(aS1 + nf, g_xh + aG1 + k0, 16);
                cp_async16(bS0 + nf, g_dh + bG0 + k0, bV0);
                cp_async16(bS1 + nf, g_dh + bG1 + k0, bV1);
                cp_commit();
                cp_wait<1>();
            } else {
                cp_wait<0>();
            }
            __syncthreads();

            uint32_t b[4][4];
            #pragma unroll
            for (int nt = 0; nt < 4; ++nt)
                ldm_x4(b[nt][0], b[nt][1], b[nt][2], b[nt][3],
                       bLd + off + (nt * 8 * PAD) * 2);

            #pragma unroll
            for (int ks = 0; ks < 2; ++ks) {
                uint32_t a[4][4];
                #pragma unroll
                for (int mt = 0; mt < 4; ++mt)
                    ldm_x4(a[mt][0], a[mt][1], a[mt][2], a[mt][3],
                           aLd + off + (mt * 16 * PAD + ks * 16) * 2);
                #pragma unroll
                for (int mt = 0; mt < 4; ++mt)
                    #pragma unroll
                    for (int nt = 0; nt < 4; ++nt)
                        mma_f16acc(acc[mt][nt][0], acc[mt][nt][1],
                                   a[mt][0], a[mt][1], a[mt][2], a[mt][3],
                                   b[nt][ks * 2], b[nt][ks * 2 + 1]);
            }
            __syncthreads();
        }

        // stage x2 / d2 (+inf pad) — buffers dead
        float* s_x2 = (float*)&sm[0][0];
        float* s_d2 = s_x2 + BM;
        if (tid < BM) s_x2[tid] = g_x2[bm + tid];
        else if (tid < BM + BN) {
            int gn = bn + tid - BM;
            s_d2[tid - BM] = (gn < NPTS) ? g_d2[gn] : __int_as_float(0x7f800000);
        }
        __syncthreads();

        // epilogue: acc[..][0] -> row rA cols cl,cl+1 ; acc[..][1] -> row rA+8
        #pragma unroll
        for (int mt = 0; mt < 4; ++mt) {
            const int rA = warp_m * 64 + mt * 16 + (lane >> 2);
            const float x2a = s_x2[rA];
            const float x2b = s_x2[rA + 8];
            float* rowA = g_dot + (size_t)(bm + rA) * PITCH + bn;
            float* rowB = rowA + (size_t)8 * PITCH;
            #pragma unroll
            for (int nt = 0; nt < 4; ++nt) {
                const int cl = warp_n * 32 + nt * 8 + (lane & 3) * 2;
                const float d2a = s_d2[cl], d2b = s_d2[cl + 1];
                float2 dA = __half22float2(*reinterpret_cast<__half2*>(&acc[mt][nt][0]));
                float2 dB = __half22float2(*reinterpret_cast<__half2*>(&acc[mt][nt][1]));
                float2 v0, v1;
                v0.x = fmaxf(fmaf(-2.f, dA.x, x2a + d2a), 0.f);
                v0.y = fmaxf(fmaf(-2.f, dA.y, x2a + d2b), 0.f);
                v1.x = fmaxf(fmaf(-2.f, dB.x, x2b + d2a), 0.f);
                v1.y = fmaxf(fmaf(-2.f, dB.y, x2b + d2b), 0.f);
                *(float2*)(rowA + cl) = v0;
                *(float2*)(rowB + cl) = v1;
            }
        }
    } else {
        // =================== FFMA path (exact fp32 SGEMM) ===================
        // All FFMA tiles fully in-bounds (bn+128 <= 40960 < NPTS).
        float* As = (float*)&sm[0][0];            // [8][128]
        float* Bs = As + 8 * 128;                 // [8][128]

        const int lr = tid >> 1;
        const int lc = (tid & 1) << 2;
        const float* Ap = Af + (size_t)(bm + lr) * D + lc;
        const float* Bp = Bf + (size_t)(bn + lr) * D + lc;

        const int tx = tid & 15;
        const int ty = tid >> 4;

        float facc[8][8];
        #pragma unroll
        for (int i = 0; i < 8; ++i)
            #pragma unroll
            for (int j = 0; j < 8; ++j)
                facc[i][j] = 0.f;

        for (int k0 = 0; k0 < D; k0 += 8) {
            float4 a4 = *(const float4*)Ap;
            float4 b4 = *(const float4*)Bp;
            Ap += 8;
            Bp += 8;

            __syncthreads();
            As[(lc + 0) * 128 + lr] = a4.x;
            As[(lc + 1) * 128 + lr] = a4.y;
            As[(lc + 2) * 128 + lr] = a4.z;
            As[(lc + 3) * 128 + lr] = a4.w;
            Bs[(lc + 0) * 128 + lr] = b4.x;
            Bs[(lc + 1) * 128 + lr] = b4.y;
            Bs[(lc + 2) * 128 + lr] = b4.z;
            Bs[(lc + 3) * 128 + lr] = b4.w;
            __syncthreads();

            #pragma unroll
            for (int kk = 0; kk < 8; ++kk) {
                float ar[8], br[8];
                *(float4*)&ar[0] = *(const float4*)&As[kk * 128 + ty * 8 + 0];
                *(float4*)&ar[4] = *(const float4*)&As[kk * 128 + ty * 8 + 4];
                *(float4*)&br[0] = *(const float4*)&Bs[kk * 128 + tx * 8 + 0];
                *(float4*)&br[4] = *(const float4*)&Bs[kk * 128 + tx * 8 + 4];
                #pragma unroll
                for (int i = 0; i < 8; ++i)
                    #pragma unroll
                    for (int j = 0; j < 8; ++j)
                        facc[i][j] = fmaf(ar[i], br[j], facc[i][j]);
            }
        }

        // exact score epilogue (x2/d2 from L2-resident globals)
        #pragma unroll
        for (int i = 0; i < 8; ++i) {
            const int gm = bm + ty * 8 + i;
            const float x2q = g_x2[gm];
            float* orow = g_dot + (size_t)gm * PITCH + bn + tx * 8;
            float4 v0, v1;
            float* vf0 = (float*)&v0;
            float* vf1 = (float*)&v1;
            #pragma unroll
            for (int j = 0; j < 4; ++j) {
                vf0[j] = fmaxf(fmaf(-2.f, facc[i][j],     x2q + g_d2[bn + tx * 8 + j]),     0.f);
                vf1[j] = fmaxf(fmaf(-2.f, facc[i][j + 4], x2q + g_d2[bn + tx * 8 + j + 4]), 0.f);
            }
            *(float4*)(orow + 0) = v0;
            *(float4*)(orow + 4) = v1;
        }
    }
}

// ---------------------------------------------------------------------------
// Kernel 2: per-query approx top-32 -> exact fp32 re-rank -> top-10 -> mode
// One block per query, 256 threads.
// ---------------------------------------------------------------------------
#define KLOC 8    // per-thread approx candidates
#define KSEL 32   // approx candidates re-ranked exactly

__global__ void __launch_bounds__(256) select_kernel(const float* __restrict__ X,
                                                     const float* __restrict__ data,
                                                     const int* __restrict__ t32,
                                                     float* __restrict__ out)
{
    const int q    = blockIdx.x;
    const int tid  = threadIdx.x;
    const int wid  = tid >> 5;
    const int lane = tid & 31;

    __shared__ float sx[D];
    sx[tid]       = X[(size_t)q * D + tid];
    sx[tid + 256] = X[(size_t)q * D + 256 + tid];

    // Phase 1: per-thread top-8 over scores (float4 reads)
    const float4* row4 = (const float4*)(g_dot + (size_t)q * PITCH);
    const unsigned long long MAXK = ~0ull;
    unsigned long long best[KLOC];
    #pragma unroll
    for (int i = 0; i < KLOC; ++i) best[i] = MAXK;

    for (int j4 = tid; j4 < PITCH / 4; j4 += 256) {
        float4 v = row4[j4];
        const float* f = (const float*)&v;
        #pragma unroll
        for (int e = 0; e < 4; ++e) {
            unsigned long long key =
                ((unsigned long long)__float_as_uint(f[e]) << 32) | (unsigned)(j4 * 4 + e);
            if (key < best[KLOC - 1]) {
                best[KLOC - 1] = key;
                #pragma unroll
                for (int i = KLOC - 1; i >= 1; --i) {
                    if (best[i] < best[i - 1]) {
                        unsigned long long t = best[i - 1];
                        best[i - 1] = best[i];
                        best[i] = t;
                    }
                }
            }
        }
    }

    // Phase 2: 32 rounds of block-wide min-merge (shuffle + 2 bars/round)
    __shared__ unsigned long long wmin[8];
    __shared__ unsigned long long winner;
    __shared__ unsigned long long topk[KSEL];
    int ptr = 0;
    for (int r = 0; r < KSEL; ++r) {
        unsigned long long my = (ptr < KLOC) ? best[ptr] : MAXK;
        unsigned long long wm = my;
        #pragma unroll
        for (int off = 16; off; off >>= 1) {
            unsigned long long o = __shfl_xor_sync(0xffffffffu, wm, off);
            if (o < wm) wm = o;
        }
        if (lane == 0) wmin[wid] = wm;
        __syncthreads();
        if (tid == 0) {
            unsigned long long w = wmin[0];
            #pragma unroll
            for (int i = 1; i < 8; ++i)
                if (wmin[i] < w) w = wmin[i];
            winner = w;
            topk[r] = w;
        }
        __syncthreads();
        unsigned long long w = winner;
        if (my == w && my != MAXK) ++ptr;   // keys unique (idx in low bits)
    }

    // Phase 3: exact fp32 re-rank of the 32 candidates (one warp each)
    __shared__ unsigned long long ex[KSEL];
    const float x2q = g_x2[q];
    for (int t = wid; t < KSEL; t += 8) {
        unsigned c = (unsigned)(topk[t] & 0xffffffffu);
        const float* dr = data + (size_t)c * D;
        float dot = 0.f;
        #pragma unroll 4
        for (int k = lane; k < D; k += 32)
            dot = fmaf(sx[k], dr[k], dot);
        #pragma unroll
        for (int off = 16; off; off >>= 1)
            dot += __shfl_down_sync(0xffffffffu, dot, off);
        if (lane == 0) {
            float sq = fmaxf(fmaf(-2.f, dot, x2q + g_d2[c]), 0.f);
            ex[t] = ((unsigned long long)__float_as_uint(sq) << 32) | c;
        }
    }
    __syncthreads();

    // Phase 4: top-10 of 32 by selection, labels, mode (smallest label on tie)
    if (tid == 0) {
        unsigned long long a[KSEL];
        #pragma unroll
        for (int i = 0; i < KSEL; ++i) a[i] = ex[i];
        #pragma unroll
        for (int r = 0; r < KNN; ++r) {
            int bi = r;
            for (int i = r + 1; i < KSEL; ++i)
                if (a[i] < a[bi]) bi = i;
            unsigned long long t = a[r]; a[r] = a[bi]; a[bi] = t;
        }

        // targets element width probe (int32 vs int64 little-endian)
        int stride = 2;
        #pragma unroll
        for (int i = 1; i < 64; i += 2)
            if (t32[i] != 0) { stride = 1; break; }

        int lab[KNN];
        #pragma unroll
        for (int r = 0; r < KNN; ++r)
            lab[r] = t32[(size_t)(unsigned)(a[r] & 0xffffffffu) * stride];

        int bestLab = 0x7fffffff, bestCnt = 0;
        #pragma unroll
        for (int i = 0; i < KNN; ++i) {
            int cnt = 0;
            #pragma unroll
            for (int j = 0; j < KNN; ++j)
                cnt += (lab[j] == lab[i]);
            if (cnt > bestCnt || (cnt == bestCnt && lab[i] < bestLab)) {
                bestCnt = cnt;
                bestLab = lab[i];
            }
        }
        out[q] = (float)bestLab;
    }
}

// ---------------------------------------------------------------------------
extern "C" void kernel_launch(void* const* d_in, const int* in_sizes, int n_in,
                              void* d_out, int out_size)
{
    const float* X       = (const float*)d_in[0];
    const float* data    = (const float*)d_in[1];
    const int*   targets = (const int*)d_in[2];
    float*       out     = (float*)d_out;

    (void)in_sizes; (void)n_in; (void)out_size;

    // convert + norms: warp per row
    int nwarps  = Q + NPTS;
    int nblocks = (nwarps + 7) / 8;
    convert_norms_kernel<<<nblocks, 256>>>(X, data);

    // hybrid GEMM: 391 N-tiles x 8 M-tiles (40 FFMA tiles interleaved)
    dim3 grid(NTILES, Q / BM);
    gemm_hybrid_kernel<<<grid, 256>>>(X, data);

    // approx select + exact re-rank + mode
    select_kernel<<<Q, 256>>>(X, data, targets, out);
}

// round 10
// speedup vs baseline: 2.3868x; 2.3868x over previous
#include <cuda_runtime.h>
#include <cuda_fp16.h>
#include <cstdint>

// Problem constants
#define Q      1024
#define D      512
#define NPTS   50000
#define BM     128
#define BN     128
#define BK     32
#define ITERS  (D / BK)                 // 16
#define NTILES ((NPTS + BN - 1) / BN)   // 391
#define KNN    10
#define PAD    40                       // padded smem row stride in b16 units (80B)
#define CPT    16                       // candidates per (row, tile): 4 quarters x top-4
#define NCAND  (NTILES * CPT)           // 6256 per query

// Scratch (device globals: allocation-free rule)
__device__ float    g_x2[Q];
__device__ float    g_d2[NPTS];
__device__ __half   g_xh[(size_t)Q * D];
__device__ __half   g_dh[(size_t)NPTS * D];
__device__ uint32_t g_cand[(size_t)Q * NCAND];   // ~25.6 MB

// ---------------------------------------------------------------------------
// helpers
// ---------------------------------------------------------------------------
__device__ __forceinline__ uint32_t smem_u32(const void* p) {
    uint32_t a;
    asm("{ .reg .u64 t; cvta.to.shared.u64 t, %1; cvt.u32.u64 %0, t; }" : "=r"(a) : "l"(p));
    return a;
}
__device__ __forceinline__ void cp_async16(uint32_t saddr, const void* gaddr, uint32_t src_sz) {
    asm volatile("cp.async.cg.shared.global [%0], [%1], 16, %2;"
                 :: "r"(saddr), "l"(gaddr), "r"(src_sz) : "memory");
}
__device__ __forceinline__ void cp_commit() {
    asm volatile("cp.async.commit_group;" ::: "memory");
}
template <int N>
__device__ __forceinline__ void cp_wait() {
    asm volatile("cp.async.wait_group %0;" :: "n"(N) : "memory");
}
__device__ __forceinline__ void ldm_x4(uint32_t& r0, uint32_t& r1, uint32_t& r2, uint32_t& r3,
                                       uint32_t addr) {
    asm volatile("ldmatrix.sync.aligned.m8n8.x4.shared.b16 {%0,%1,%2,%3}, [%4];"
                 : "=r"(r0), "=r"(r1), "=r"(r2), "=r"(r3) : "r"(addr));
}
// f16 x f16 -> f16 accum: D/C are 2 b32 regs packing {c0,c1} / {c2,c3}
__device__ __forceinline__ void mma_f16acc(uint32_t& d0, uint32_t& d1,
                                           uint32_t a0, uint32_t a1, uint32_t a2, uint32_t a3,
                                           uint32_t b0, uint32_t b1) {
    asm volatile(
        "mma.sync.aligned.m16n8k16.row.col.f16.f16.f16.f16 "
        "{%0,%1}, {%2,%3,%4,%5}, {%6,%7}, {%0,%1};"
        : "+r"(d0), "+r"(d1)
        : "r"(a0), "r"(a1), "r"(a2), "r"(a3), "r"(b0), "r"(b1));
}

// ---------------------------------------------------------------------------
// Kernel 0: fused fp32->fp16 convert + row squared norms (warp per row)
// ---------------------------------------------------------------------------
__global__ void convert_norms_kernel(const float* __restrict__ X,
                                     const float* __restrict__ data)
{
    int warp = (blockIdx.x * blockDim.x + threadIdx.x) >> 5;
    int lane = threadIdx.x & 31;
    if (warp >= Q + NPTS) return;

    const float* src;
    __half*      dsth;
    float*       dstn;
    int row;
    if (warp < Q) { src = X;    row = warp;     dsth = g_xh; dstn = g_x2; }
    else          { src = data; row = warp - Q; dsth = g_dh; dstn = g_d2; }

    const float4* s4 = (const float4*)(src + (size_t)row * D);
    uint2*        d8 = (uint2*)(dsth + (size_t)row * D);

    float s = 0.f;
    #pragma unroll
    for (int it = 0; it < 4; ++it) {
        int i = it * 32 + lane;
        float4 v = s4[i];
        s = fmaf(v.x, v.x, s);
        s = fmaf(v.y, v.y, s);
        s = fmaf(v.z, v.z, s);
        s = fmaf(v.w, v.w, s);
        __half2 h0 = __floats2half2_rn(v.x, v.y);
        __half2 h1 = __floats2half2_rn(v.z, v.w);
        uint2 w;
        w.x = *reinterpret_cast<uint32_t*>(&h0);
        w.y = *reinterpret_cast<uint32_t*>(&h1);
        d8[i] = w;
    }
    #pragma unroll
    for (int off = 16; off; off >>= 1)
        s += __shfl_down_sync(0xffffffffu, s, off);
    if (lane == 0) dstn[row] = s;
}

// ---------------------------------------------------------------------------
// Kernel 1: f16 mma.sync GEMM tile (128x128, K=512, f16 accum) with FUSED
// selection epilogue: per row, per 32-col quarter, write the top-4 approx
// scores as u32 keys (half_bits << 16 | global_col) to g_cand.
// ---------------------------------------------------------------------------
__global__ void __launch_bounds__(256, 2) gemm_mma_kernel()
{
    // 40KB: pipeline = 2 x (A 10240B + B 10240B); epilogue reuses as
    // [x2 128f][d2 128f][score tile 64 x 130 f]
    __shared__ __align__(16) uint16_t sm[2][BM * PAD + BN * PAD];

    const int tid    = threadIdx.x;
    const int wid    = tid >> 5;
    const int lane   = tid & 31;
    const int warp_m = wid >> 2;    // 0..1
    const int warp_n = wid & 3;     // 0..3
    const int bx     = blockIdx.x;
    const int bn     = bx * BN;
    const int bm     = blockIdx.y * BM;

    // cp.async per-thread mapping: 512 16B-chunks per operand tile, 2/thread
    const int r0 = tid >> 2,         c0 = tid & 3;
    const int r1 = (tid + 256) >> 2, c1 = (tid + 256) & 3;

    const uint32_t sA  = smem_u32(&sm[0][0]);
    const uint32_t sB  = sA + BM * PAD * 2;
    const uint32_t BUF = (BM * PAD + BN * PAD) * 2;   // bytes per stage

    const uint32_t aS0 = sA + (r0 * PAD + c0 * 8) * 2;
    const uint32_t aS1 = sA + (r1 * PAD + c1 * 8) * 2;
    const uint32_t bS0 = sB + (r0 * PAD + c0 * 8) * 2;
    const uint32_t bS1 = sB + (r1 * PAD + c1 * 8) * 2;
    const size_t   aG0 = (size_t)(bm + r0) * D + c0 * 8;
    const size_t   aG1 = (size_t)(bm + r1) * D + c1 * 8;
    const size_t   bG0 = (size_t)(bn + r0) * D + c0 * 8;
    const size_t   bG1 = (size_t)(bn + r1) * D + c1 * 8;
    const uint32_t bV0 = (bn + r0 < NPTS) ? 16u : 0u;
    const uint32_t bV1 = (bn + r1 < NPTS) ? 16u : 0u;

    // ldmatrix per-lane bases (mapping proven in R5/R9)
    const uint32_t aLd = sA + (((warp_m * 64) + (lane & 15)) * PAD + (lane >> 4) * 8) * 2;
    const uint32_t bLd = sB + (((warp_n * 32) + (lane & 7)) * PAD + (lane >> 3) * 8) * 2;

    uint32_t acc[4][4][2];   // f16x2 accumulators
    #pragma unroll
    for (int i = 0; i < 4; ++i)
        #pragma unroll
        for (int j = 0; j < 4; ++j)
            acc[i][j][0] = acc[i][j][1] = 0u;

    // prologue: iter 0 -> buf 0
    cp_async16(aS0, g_xh + aG0, 16);
    cp_async16(aS1, g_xh + aG1, 16);
    cp_async16(bS0, g_dh + bG0, bV0);
    cp_async16(bS1, g_dh + bG1, bV1);
    cp_commit();

    for (int it = 0; it < ITERS; ++it) {
        const uint32_t off = (it & 1) ? BUF : 0;

        if (it + 1 < ITERS) {
            const uint32_t nf = ((it + 1) & 1) ? BUF : 0;
            const int      k0 = (it + 1) * BK;
            cp_async16(aS0 + nf, g_xh + aG0 + k0, 16);
            cp_async16(aS1 + nf, g_xh + aG1 + k0, 16);
            cp_async16(bS0 + nf, g_dh + bG0 + k0, bV0);
            cp_async16(bS1 + nf, g_dh + bG1 + k0, bV1);
            cp_commit();
            cp_wait<1>();
        } else {
            cp_wait<0>();
        }
        __syncthreads();

        uint32_t b[4][4];
        #pragma unroll
        for (int nt = 0; nt < 4; ++nt)
            ldm_x4(b[nt][0], b[nt][1], b[nt][2], b[nt][3],
                   bLd + off + (nt * 8 * PAD) * 2);

        #pragma unroll
        for (int ks = 0; ks < 2; ++ks) {
            uint32_t a[4][4];
            #pragma unroll
            for (int mt = 0; mt < 4; ++mt)
                ldm_x4(a[mt][0], a[mt][1], a[mt][2], a[mt][3],
                       aLd + off + (mt * 16 * PAD + ks * 16) * 2);
            #pragma unroll
            for (int mt = 0; mt < 4; ++mt)
                #pragma unroll
                for (int nt = 0; nt < 4; ++nt)
                    mma_f16acc(acc[mt][nt][0], acc[mt][nt][1],
                               a[mt][0], a[mt][1], a[mt][2], a[mt][3],
                               b[nt][ks * 2], b[nt][ks * 2 + 1]);
        }
        __syncthreads();
    }

    // ---------------- fused selection epilogue ----------------
    float* s_x2 = (float*)&sm[0][0];          // [128]
    float* s_d2 = s_x2 + BM;                  // [128]
    float* sc   = s_d2 + BN;                  // [64][130] score tile (33.3KB)

    if (tid < BM) s_x2[tid] = g_x2[bm + tid];
    else {
        int gn = bn + tid - BM;
        s_d2[tid - BM] = (gn < NPTS) ? g_d2[gn] : __int_as_float(0x7f800000);
    }
    __syncthreads();

    #pragma unroll
    for (int p = 0; p < 2; ++p) {
        if (warp_m == p) {
            #pragma unroll
            for (int mt = 0; mt < 4; ++mt) {
                const int r   = mt * 16 + (lane >> 2);          // local row in pass
                const float x2a = s_x2[p * 64 + r];
                const float x2b = s_x2[p * 64 + r + 8];
                #pragma unroll
                for (int nt = 0; nt < 4; ++nt) {
                    const int cl = warp_n * 32 + nt * 8 + (lane & 3) * 2;
                    const float d2a = s_d2[cl], d2b = s_d2[cl + 1];
                    float2 dA = __half22float2(*reinterpret_cast<__half2*>(&acc[mt][nt][0]));
                    float2 dB = __half22float2(*reinterpret_cast<__half2*>(&acc[mt][nt][1]));
                    sc[r * 130 + cl]           = fmaxf(fmaf(-2.f, dA.x, x2a + d2a), 0.f);
                    sc[r * 130 + cl + 1]       = fmaxf(fmaf(-2.f, dA.y, x2a + d2b), 0.f);
                    sc[(r + 8) * 130 + cl]     = fmaxf(fmaf(-2.f, dB.x, x2b + d2a), 0.f);
                    sc[(r + 8) * 130 + cl + 1] = fmaxf(fmaf(-2.f, dB.y, x2b + d2b), 0.f);
                }
            }
        }
        __syncthreads();

        // per-row, per-quarter top-4: 256 threads = 64 rows x 4 quarters
        {
            const int row_l = tid >> 2;
            const int qd    = tid & 3;
            uint32_t top[4] = {0xffffffffu, 0xffffffffu, 0xffffffffu, 0xffffffffu};
            #pragma unroll 8
            for (int i = 0; i < 32; ++i) {
                const int col = qd * 32 + i;
                float s = sc[row_l * 130 + col];
                uint32_t hb = (uint32_t)__half_as_ushort(__float2half_rn(s));
                uint32_t key = (hb << 16) | (uint32_t)(bn + col);
                if (key < top[3]) {
                    top[3] = key;
                    #pragma unroll
                    for (int k = 3; k >= 1; --k)
                        if (top[k] < top[k - 1]) { uint32_t t = top[k - 1]; top[k - 1] = top[k]; top[k] = t; }
                }
            }
            const int gq = bm + p * 64 + row_l;
            uint4 w = make_uint4(top[0], top[1], top[2], top[3]);
            *(uint4*)&g_cand[(size_t)gq * NCAND + bx * CPT + qd * 4] = w;
        }
        __syncthreads();
    }
}

// ---------------------------------------------------------------------------
// Kernel 2: per-query scan 6256 candidate keys -> top-32 -> exact fp32
// re-rank -> top-10 -> mode. One block per query, 256 threads.
// ---------------------------------------------------------------------------
#define KLOC 8    // per-thread candidates
#define KSEL 32   // candidates re-ranked exactly

__global__ void __launch_bounds__(256) select_kernel(const float* __restrict__ X,
                                                     const float* __restrict__ data,
                                                     const int* __restrict__ t32,
                                                     float* __restrict__ out)
{
    const int q    = blockIdx.x;
    const int tid  = threadIdx.x;
    const int wid  = tid >> 5;
    const int lane = tid & 31;

    __shared__ float sx[D];
    sx[tid]       = X[(size_t)q * D + tid];
    sx[tid + 256] = X[(size_t)q * D + 256 + tid];

    // Phase 1: per-thread top-8 over candidate keys (uint4 reads)
    const uint4* cand4 = (const uint4*)&g_cand[(size_t)q * NCAND];
    const uint32_t MAXK = 0xffffffffu;
    uint32_t best[KLOC];
    #pragma unroll
    for (int i = 0; i < KLOC; ++i) best[i] = MAXK;

    for (int j = tid; j < NCAND / 4; j += 256) {
        uint4 v = cand4[j];
        const uint32_t w[4] = {v.x, v.y, v.z, v.w};
        #pragma unroll
        for (int e = 0; e < 4; ++e) {
            uint32_t key = w[e];
            if (key < best[KLOC - 1]) {
                best[KLOC - 1] = key;
                #pragma unroll
                for (int i = KLOC - 1; i >= 1; --i) {
                    if (best[i] < best[i - 1]) {
                        uint32_t t = best[i - 1];
                        best[i - 1] = best[i];
                        best[i] = t;
                    }
                }
            }
        }
    }

    // Phase 2: 32 rounds of block-wide min-merge
    __shared__ uint32_t wmin[8];
    __shared__ uint32_t winner;
    __shared__ uint32_t topk[KSEL];
    int ptr = 0;
    for (int r = 0; r < KSEL; ++r) {
        uint32_t my = (ptr < KLOC) ? best[ptr] : MAXK;
        uint32_t wm = my;
        #pragma unroll
        for (int off = 16; off; off >>= 1)
            wm = min(wm, __shfl_xor_sync(0xffffffffu, wm, off));
        if (lane == 0) wmin[wid] = wm;
        __syncthreads();
        if (tid == 0) {
            uint32_t w = wmin[0];
            #pragma unroll
            for (int i = 1; i < 8; ++i) w = min(w, wmin[i]);
            winner = w;
            topk[r] = w;
        }
        __syncthreads();
        if (my == winner && my != MAXK) ++ptr;   // keys unique (col in low bits)
    }

    // Phase 3: exact fp32 re-rank of the 32 candidates (one warp each, strided)
    __shared__ unsigned long long ex[KSEL];
    const float x2q = g_x2[q];
    for (int t = wid; t < KSEL; t += 8) {
        unsigned c = topk[t] & 0xffffu;
        const float* dr = data + (size_t)c * D;
        float dot = 0.f;
        #pragma unroll 4
        for (int k = lane; k < D; k += 32)
            dot = fmaf(sx[k], dr[k], dot);
        #pragma unroll
        for (int off = 16; off; off >>= 1)
            dot += __shfl_down_sync(0xffffffffu, dot, off);
        if (lane == 0) {
            float sq = fmaxf(fmaf(-2.f, dot, x2q + g_d2[c]), 0.f);
            ex[t] = ((unsigned long long)__float_as_uint(sq) << 32) | c;
        }
    }
    __syncthreads();

    // Phase 4: top-10 of 32 by selection, labels, mode (smallest label on tie)
    if (tid == 0) {
        unsigned long long a[KSEL];
        #pragma unroll
        for (int i = 0; i < KSEL; ++i) a[i] = ex[i];
        #pragma unroll
        for (int r = 0; r < KNN; ++r) {
            int bi = r;
            for (int i = r + 1; i < KSEL; ++i)
                if (a[i] < a[bi]) bi = i;
            unsigned long long t = a[r]; a[r] = a[bi]; a[bi] = t;
        }

        // targets element width probe (int32 vs int64 little-endian)
        int stride = 2;
        #pragma unroll
        for (int i = 1; i < 64; i += 2)
            if (t32[i] != 0) { stride = 1; break; }

        int lab[KNN];
        #pragma unroll
        for (int r = 0; r < KNN; ++r)
            lab[r] = t32[(size_t)(unsigned)(a[r] & 0xffffffffu) * stride];

        int bestLab = 0x7fffffff, bestCnt = 0;
        #pragma unroll
        for (int i = 0; i < KNN; ++i) {
            int cnt = 0;
            #pragma unroll
            for (int j = 0; j < KNN; ++j)
                cnt += (lab[j] == lab[i]);
            if (cnt > bestCnt || (cnt == bestCnt && lab[i] < bestLab)) {
                bestCnt = cnt;
                bestLab = lab[i];
            }
        }
        out[q] = (float)bestLab;
    }
}

// ---------------------------------------------------------------------------
extern "C" void kernel_launch(void* const* d_in, const int* in_sizes, int n_in,
                              void* d_out, int out_size)
{
    const float* X       = (const float*)d_in[0];
    const float* data    = (const float*)d_in[1];
    const int*   targets = (const int*)d_in[2];
    float*       out     = (float*)d_out;

    (void)in_sizes; (void)n_in; (void)out_size;

    // convert + norms: warp per row
    int nwarps  = Q + NPTS;
    int nblocks = (nwarps + 7) / 8;
    convert_norms_kernel<<<nblocks, 256>>>(X, data);

    // f16 mma.sync GEMM with fused candidate selection
    dim3 grid(NTILES, Q / BM);
    gemm_mma_kernel<<<grid, 256>>>();

    // candidate merge + exact re-rank + mode
    select_kernel<<<Q, 256>>>(X, data, targets, out);
}

// round 14
// speedup vs baseline: 2.4990x; 1.0470x over previous
#include <cuda_runtime.h>
#include <cuda_fp16.h>
#include <cstdint>

// Problem constants
#define Q      1024
#define D      512
#define NPTS   50000
#define BM     128
#define BN     128
#define BK     32
#define ITERS  (D / BK)                 // 16
#define NTILES ((NPTS + BN - 1) / BN)   // 391
#define KNN    10
#define PAD    40                       // padded smem row stride in b16 units (80B)
#define CPT    16                       // candidates per (row, tile): 4 quarters x top-4
#define NCAND  (NTILES * CPT)           // 6256 per query

// Scratch (device globals: allocation-free rule)
__device__ float    g_x2[Q];
__device__ float    g_d2[NPTS];
__device__ __half   g_xh[(size_t)Q * D];
__device__ __half   g_dh[(size_t)NPTS * D];
__device__ uint32_t g_cand[(size_t)Q * NCAND];   // ~25.6 MB

// ---------------------------------------------------------------------------
// helpers
// ---------------------------------------------------------------------------
__device__ __forceinline__ uint32_t smem_u32(const void* p) {
    uint32_t a;
    asm("{ .reg .u64 t; cvta.to.shared.u64 t, %1; cvt.u32.u64 %0, t; }" : "=r"(a) : "l"(p));
    return a;
}
__device__ __forceinline__ void cp_async16(uint32_t saddr, const void* gaddr, uint32_t src_sz) {
    asm volatile("cp.async.cg.shared.global [%0], [%1], 16, %2;"
                 :: "r"(saddr), "l"(gaddr), "r"(src_sz) : "memory");
}
__device__ __forceinline__ void cp_commit() {
    asm volatile("cp.async.commit_group;" ::: "memory");
}
template <int N>
__device__ __forceinline__ void cp_wait() {
    asm volatile("cp.async.wait_group %0;" :: "n"(N) : "memory");
}
__device__ __forceinline__ void ldm_x4(uint32_t& r0, uint32_t& r1, uint32_t& r2, uint32_t& r3,
                                       uint32_t addr) {
    asm volatile("ldmatrix.sync.aligned.m8n8.x4.shared.b16 {%0,%1,%2,%3}, [%4];"
                 : "=r"(r0), "=r"(r1), "=r"(r2), "=r"(r3) : "r"(addr));
}
// f16 x f16 -> f16 accum: D/C are 2 b32 regs packing {c0,c1} / {c2,c3}
__device__ __forceinline__ void mma_f16acc(uint32_t& d0, uint32_t& d1,
                                           uint32_t a0, uint32_t a1, uint32_t a2, uint32_t a3,
                                           uint32_t b0, uint32_t b1) {
    asm volatile(
        "mma.sync.aligned.m16n8k16.row.col.f16.f16.f16.f16 "
        "{%0,%1}, {%2,%3,%4,%5}, {%6,%7}, {%0,%1};"
        : "+r"(d0), "+r"(d1)
        : "r"(a0), "r"(a1), "r"(a2), "r"(a3), "r"(b0), "r"(b1));
}
// sorted-ascending top-4 insert
__device__ __forceinline__ void ins4(uint32_t* t, uint32_t key) {
    if (key < t[3]) {
        t[3] = key;
        #pragma unroll
        for (int k = 3; k >= 1; --k)
            if (t[k] < t[k - 1]) { uint32_t tmp = t[k - 1]; t[k - 1] = t[k]; t[k] = tmp; }
    }
}

// ---------------------------------------------------------------------------
// Kernel 0: fused fp32->fp16 convert + row squared norms (warp per row)
// ---------------------------------------------------------------------------
__global__ void convert_norms_kernel(const float* __restrict__ X,
                                     const float* __restrict__ data)
{
    int warp = (blockIdx.x * blockDim.x + threadIdx.x) >> 5;
    int lane = threadIdx.x & 31;
    if (warp >= Q + NPTS) return;

    const float* src;
    __half*      dsth;
    float*       dstn;
    int row;
    if (warp < Q) { src = X;    row = warp;     dsth = g_xh; dstn = g_x2; }
    else          { src = data; row = warp - Q; dsth = g_dh; dstn = g_d2; }

    const float4* s4 = (const float4*)(src + (size_t)row * D);
    uint2*        d8 = (uint2*)(dsth + (size_t)row * D);

    float s = 0.f;
    #pragma unroll
    for (int it = 0; it < 4; ++it) {
        int i = it * 32 + lane;
        float4 v = s4[i];
        s = fmaf(v.x, v.x, s);
        s = fmaf(v.y, v.y, s);
        s = fmaf(v.z, v.z, s);
        s = fmaf(v.w, v.w, s);
        __half2 h0 = __floats2half2_rn(v.x, v.y);
        __half2 h1 = __floats2half2_rn(v.z, v.w);
        uint2 w;
        w.x = *reinterpret_cast<uint32_t*>(&h0);
        w.y = *reinterpret_cast<uint32_t*>(&h1);
        d8[i] = w;
    }
    #pragma unroll
    for (int off = 16; off; off >>= 1)
        s += __shfl_down_sync(0xffffffffu, s, off);
    if (lane == 0) dstn[row] = s;
}

// ---------------------------------------------------------------------------
// Kernel 1: f16 mma.sync GEMM tile (128x128, K=512, f16 accum) with a fully
// register-resident selection epilogue: per row, per 32-col quarter, the
// warp computes top-4 approx keys (half_bits << 16 | global_col) via local
// insert + 2-round xor-shuffle merge, then writes them to g_cand.
// ---------------------------------------------------------------------------
__global__ void __launch_bounds__(256, 2) gemm_mma_kernel()
{
    // 40KB: pipeline = 2 x (A 10240B + B 10240B); epilogue aliases [x2][d2].
    __shared__ __align__(16) uint16_t sm[2][BM * PAD + BN * PAD];

    const int tid    = threadIdx.x;
    const int wid    = tid >> 5;
    const int lane   = tid & 31;
    const int warp_m = wid >> 2;    // 0..1
    const int warp_n = wid & 3;     // 0..3
    const int bx     = blockIdx.x;
    const int bn     = bx * BN;
    const int bm     = blockIdx.y * BM;

    // cp.async per-thread mapping: 512 16B-chunks per operand tile, 2/thread
    const int r0 = tid >> 2,         c0 = tid & 3;
    const int r1 = (tid + 256) >> 2, c1 = (tid + 256) & 3;

    const uint32_t sA  = smem_u32(&sm[0][0]);
    const uint32_t sB  = sA + BM * PAD * 2;
    const uint32_t BUF = (BM * PAD + BN * PAD) * 2;   // bytes per stage

    const uint32_t aS0 = sA + (r0 * PAD + c0 * 8) * 2;
    const uint32_t aS1 = sA + (r1 * PAD + c1 * 8) * 2;
    const uint32_t bS0 = sB + (r0 * PAD + c0 * 8) * 2;
    const uint32_t bS1 = sB + (r1 * PAD + c1 * 8) * 2;
    const size_t   aG0 = (size_t)(bm + r0) * D + c0 * 8;
    const size_t   aG1 = (size_t)(bm + r1) * D + c1 * 8;
    const size_t   bG0 = (size_t)(bn + r0) * D + c0 * 8;
    const size_t   bG1 = (size_t)(bn + r1) * D + c1 * 8;
    const uint32_t bV0 = (bn + r0 < NPTS) ? 16u : 0u;
    const uint32_t bV1 = (bn + r1 < NPTS) ? 16u : 0u;

    // ldmatrix per-lane bases (mapping proven in R5/R9/R10)
    const uint32_t aLd = sA + (((warp_m * 64) + (lane & 15)) * PAD + (lane >> 4) * 8) * 2;
    const uint32_t bLd = sB + (((warp_n * 32) + (lane & 7)) * PAD + (lane >> 3) * 8) * 2;

    uint32_t acc[4][4][2];   // f16x2 accumulators
    #pragma unroll
    for (int i = 0; i < 4; ++i)
        #pragma unroll
        for (int j = 0; j < 4; ++j)
            acc[i][j][0] = acc[i][j][1] = 0u;

    // prologue: iter 0 -> buf 0
    cp_async16(aS0, g_xh + aG0, 16);
    cp_async16(aS1, g_xh + aG1, 16);
    cp_async16(bS0, g_dh + bG0, bV0);
    cp_async16(bS1, g_dh + bG1, bV1);
    cp_commit();

    for (int it = 0; it < ITERS; ++it) {
        const uint32_t off = (it & 1) ? BUF : 0;

        if (it + 1 < ITERS) {
            const uint32_t nf = ((it + 1) & 1) ? BUF : 0;
            const int      k0 = (it + 1) * BK;
            cp_async16(aS0 + nf, g_xh + aG0 + k0, 16);
            cp_async16(aS1 + nf, g_xh + aG1 + k0, 16);
            cp_async16(bS0 + nf, g_dh + bG0 + k0, bV0);
            cp_async16(bS1 + nf, g_dh + bG1 + k0, bV1);
            cp_commit();
            cp_wait<1>();
        } else {
            cp_wait<0>();
        }
        __syncthreads();

        uint32_t b[4][4];
        #pragma unroll
        for (int nt = 0; nt < 4; ++nt)
            ldm_x4(b[nt][0], b[nt][1], b[nt][2], b[nt][3],
                   bLd + off + (nt * 8 * PAD) * 2);

        #pragma unroll
        for (int ks = 0; ks < 2; ++ks) {
            uint32_t a[4][4];
            #pragma unroll
            for (int mt = 0; mt < 4; ++mt)
                ldm_x4(a[mt][0], a[mt][1], a[mt][2], a[mt][3],
                       aLd + off + (mt * 16 * PAD + ks * 16) * 2);
            #pragma unroll
            for (int mt = 0; mt < 4; ++mt)
                #pragma unroll
                for (int nt = 0; nt < 4; ++nt)
                    mma_f16acc(acc[mt][nt][0], acc[mt][nt][1],
                               a[mt][0], a[mt][1], a[mt][2], a[mt][3],
                               b[nt][ks * 2], b[nt][ks * 2 + 1]);
        }
        __syncthreads();
    }

    // ---------------- register-resident selection epilogue ----------------
    float* s_x2 = (float*)&sm[0][0];          // [128]
    float* s_d2 = s_x2 + BM;                  // [128]
    if (tid < BM) s_x2[tid] = g_x2[bm + tid];
    else {
        int gn = bn + tid - BM;
        s_d2[tid - BM] = (gn < NPTS) ? g_d2[gn] : __int_as_float(0x7f800000);
    }
    __syncthreads();

    // Warp owns rows warp_m*64..+63, cols (quarter) warp_n*32..+31.
    // Lane layout: groupRow = lane>>2 (0..7), colPair = lane&3 (cols cl,cl+1).
    // Lanes {base..base+3} (base = lane & ~3) share each row -> shuffle merge.
    const int cqBase = warp_n * 32 + (lane & 3) * 2;
    #pragma unroll
    for (int mt = 0; mt < 4; ++mt) {
        const int rA = warp_m * 64 + mt * 16 + (lane >> 2);   // local row
        const int rB = rA + 8;
        const float x2a = s_x2[rA];
        const float x2b = s_x2[rB];

        uint32_t topA[4] = {0xffffffffu, 0xffffffffu, 0xffffffffu, 0xffffffffu};
        uint32_t topB[4] = {0xffffffffu, 0xffffffffu, 0xffffffffu, 0xffffffffu};

        #pragma unroll
        for (int nt = 0; nt < 4; ++nt) {
            const int cl = warp_n * 32 + nt * 8 + (lane & 3) * 2;
            const float d2a = s_d2[cl], d2b = s_d2[cl + 1];
            float2 dA = __half22float2(*reinterpret_cast<__half2*>(&acc[mt][nt][0]));
            float2 dB = __half22float2(*reinterpret_cast<__half2*>(&acc[mt][nt][1]));
            float sA0 = fmaxf(fmaf(-2.f, dA.x, x2a + d2a), 0.f);
            float sA1 = fmaxf(fmaf(-2.f, dA.y, x2a + d2b), 0.f);
            float sB0 = fmaxf(fmaf(-2.f, dB.x, x2b + d2a), 0.f);
            float sB1 = fmaxf(fmaf(-2.f, dB.y, x2b + d2b), 0.f);
            uint32_t c0g = (uint32_t)(bn + cl), c1g = c0g + 1;
            ins4(topA, ((uint32_t)__half_as_ushort(__float2half_rn(sA0)) << 16) | c0g);
            ins4(topA, ((uint32_t)__half_as_ushort(__float2half_rn(sA1)) << 16) | c1g);
            ins4(topB, ((uint32_t)__half_as_ushort(__float2half_rn(sB0)) << 16) | c0g);
            ins4(topB, ((uint32_t)__half_as_ushort(__float2half_rn(sB1)) << 16) | c1g);
        }

        // xor-butterfly merge across the 4 lanes sharing each row
        #pragma unroll
        for (int offx = 1; offx <= 2; offx <<= 1) {
            uint32_t oA[4], oB[4];
            #pragma unroll
            for (int k = 0; k < 4; ++k) {
                oA[k] = __shfl_xor_sync(0xffffffffu, topA[k], offx);
                oB[k] = __shfl_xor_sync(0xffffffffu, topB[k], offx);
            }
            #pragma unroll
            for (int k = 0; k < 4; ++k) {
                ins4(topA, oA[k]);
                ins4(topB, oB[k]);
            }
        }

        if ((lane & 3) == 0) {
            *(uint4*)&g_cand[(size_t)(bm + rA) * NCAND + bx * CPT + warp_n * 4] =
                make_uint4(topA[0], topA[1], topA[2], topA[3]);
            *(uint4*)&g_cand[(size_t)(bm + rB) * NCAND + bx * CPT + warp_n * 4] =
                make_uint4(topB[0], topB[1], topB[2], topB[3]);
        }
    }
    (void)cqBase;
}

// ---------------------------------------------------------------------------
// Kernel 2: per-query scan 6256 candidate keys -> top-32 -> exact fp32
// re-rank -> top-10 -> mode. One block per query, 256 threads.
// ---------------------------------------------------------------------------
#define KLOC 8    // per-thread candidates
#define KSEL 32   // candidates re-ranked exactly

__global__ void __launch_bounds__(256) select_kernel(const float* __restrict__ X,
                                                     const float* __restrict__ data,
                                                     const int* __restrict__ t32,
                                                     float* __restrict__ out)
{
    const int q    = blockIdx.x;
    const int tid  = threadIdx.x;
    const int wid  = tid >> 5;
    const int lane = tid & 31;

    __shared__ float sx[D];
    sx[tid]       = X[(size_t)q * D + tid];
    sx[tid + 256] = X[(size_t)q * D + 256 + tid];

    // Phase 1: per-thread top-8 over candidate keys (uint4 reads)
    const uint4* cand4 = (const uint4*)&g_cand[(size_t)q * NCAND];
    const uint32_t MAXK = 0xffffffffu;
    uint32_t best[KLOC];
    #pragma unroll
    for (int i = 0; i < KLOC; ++i) best[i] = MAXK;

    for (int j = tid; j < NCAND / 4; j += 256) {
        uint4 v = cand4[j];
        const uint32_t w[4] = {v.x, v.y, v.z, v.w};
        #pragma unroll
        for (int e = 0; e < 4; ++e) {
            uint32_t key = w[e];
            if (key < best[KLOC - 1]) {
                best[KLOC - 1] = key;
                #pragma unroll
                for (int i = KLOC - 1; i >= 1; --i) {
                    if (best[i] < best[i - 1]) {
                        uint32_t t = best[i - 1];
                        best[i - 1] = best[i];
                        best[i] = t;
                    }
                }
            }
        }
    }

    // Phase 2: 32 rounds of block-wide min-merge
    __shared__ uint32_t wmin[8];
    __shared__ uint32_t winner;
    __shared__ uint32_t topk[KSEL];
    int ptr = 0;
    for (int r = 0; r < KSEL; ++r) {
        uint32_t my = (ptr < KLOC) ? best[ptr] : MAXK;
        uint32_t wm = my;
        #pragma unroll
        for (int off = 16; off; off >>= 1)
            wm = min(wm, __shfl_xor_sync(0xffffffffu, wm, off));
        if (lane == 0) wmin[wid] = wm;
        __syncthreads();
        if (tid == 0) {
            uint32_t w = wmin[0];
            #pragma unroll
            for (int i = 1; i < 8; ++i) w = min(w, wmin[i]);
            winner = w;
            topk[r] = w;
        }
        __syncthreads();
        if (my == winner && my != MAXK) ++ptr;   // keys unique (col in low bits)
    }

    // Phase 3: exact fp32 re-rank of the 32 candidates (one warp each, strided)
    __shared__ unsigned long long ex[KSEL];
    const float x2q = g_x2[q];
    for (int t = wid; t < KSEL; t += 8) {
        unsigned c = topk[t] & 0xffffu;
        const float* dr = data + (size_t)c * D;
        float dot = 0.f;
        #pragma unroll 4
        for (int k = lane; k < D; k += 32)
            dot = fmaf(sx[k], dr[k], dot);
        #pragma unroll
        for (int off = 16; off; off >>= 1)
            dot += __shfl_down_sync(0xffffffffu, dot, off);
        if (lane == 0) {
            float sq = fmaxf(fmaf(-2.f, dot, x2q + g_d2[c]), 0.f);
            ex[t] = ((unsigned long long)__float_as_uint(sq) << 32) | c;
        }
    }
    __syncthreads();

    // Phase 4: top-10 of 32 by selection, labels, mode (smallest label on tie)
    if (tid == 0) {
        unsigned long long a[KSEL];
        #pragma unroll
        for (int i = 0; i < KSEL; ++i) a[i] = ex[i];
        #pragma unroll
        for (int r = 0; r < KNN; ++r) {
            int bi = r;
            for (int i = r + 1; i < KSEL; ++i)
                if (a[i] < a[bi]) bi = i;
            unsigned long long t = a[r]; a[r] = a[bi]; a[bi] = t;
        }

        // targets element width probe (int32 vs int64 little-endian)
        int stride = 2;
        #pragma unroll
        for (int i = 1; i < 64; i += 2)
            if (t32[i] != 0) { stride = 1; break; }

        int lab[KNN];
        #pragma unroll
        for (int r = 0; r < KNN; ++r)
            lab[r] = t32[(size_t)(unsigned)(a[r] & 0xffffffffu) * stride];

        int bestLab = 0x7fffffff, bestCnt = 0;
        #pragma unroll
        for (int i = 0; i < KNN; ++i) {
            int cnt = 0;
            #pragma unroll
            for (int j = 0; j < KNN; ++j)
                cnt += (lab[j] == lab[i]);
            if (cnt > bestCnt || (cnt == bestCnt && lab[i] < bestLab)) {
                bestCnt = cnt;
                bestLab = lab[i];
            }
        }
        out[q] = (float)bestLab;
    }
}

// ---------------------------------------------------------------------------
extern "C" void kernel_launch(void* const* d_in, const int* in_sizes, int n_in,
                              void* d_out, int out_size)
{
    const float* X       = (const float*)d_in[0];
    const float* data    = (const float*)d_in[1];
    const int*   targets = (const int*)d_in[2];
    float*       out     = (float*)d_out;

    (void)in_sizes; (void)n_in; (void)out_size;

    // convert + norms: warp per row
    int nwarps  = Q + NPTS;
    int nblocks = (nwarps + 7) / 8;
    convert_norms_kernel<<<nblocks, 256>>>(X, data);

    // f16 mma.sync GEMM with fused register-resident candidate selection
    dim3 grid(NTILES, Q / BM);
    gemm_mma_kernel<<<grid, 256>>>();

    // candidate merge + exact re-rank + mode
    select_kernel<<<Q, 256>>>(X, data, targets, out);
}